// round 2
// baseline (speedup 1.0000x reference)
#include <cuda_runtime.h>
#include <cuda_bf16.h>
#include <math.h>

#define NN 20000
#define NE 320000
#define NB 64
#define HID 128
#define DEPTH 4
#define NFREQ 8
#define KFK (NFREQ * HID)   // 1024
#define TWO_PI_F 6.283185307179586f

// ---------------- scratch (static device allocations; no cudaMalloc) ----------------
__device__ float g_h[NN * HID];
__device__ float g_p1[NN * HID];
__device__ float g_p2[NN * HID];
__device__ float g_hconv[NN * HID];
__device__ float g_S[NN * KFK];
__device__ float g_q1[NN];
__device__ float g_q2[NN];
__device__ float g_logits[NN];
__device__ float g_stats[2 * HID];
__device__ float g_pooled[NB * HID];
__device__ unsigned g_umax;
__device__ float g_sumexp;

// ---------------- utility ----------------
__global__ void zero_kernel(float* p, int n) {
    int i = blockIdx.x * blockDim.x + threadIdx.x;
    int stride = gridDim.x * blockDim.x;
    for (; i < n; i += stride) p[i] = 0.f;
}

__global__ void pool_init_kernel() {
    int i = blockIdx.x * blockDim.x + threadIdx.x;
    int stride = gridDim.x * blockDim.x;
    for (int j = i; j < NB * HID; j += stride) g_pooled[j] = 0.f;
    if (i == 0) { g_umax = 0u; g_sumexp = 0.f; }
}

// ---------------- node embedding: h = x @ node_w + node_b ----------------
__global__ void node_embed_kernel(const float* __restrict__ x,
                                  const float* __restrict__ w,
                                  const float* __restrict__ b) {
    int idx = blockIdx.x * blockDim.x + threadIdx.x;
    if (idx >= NN * HID) return;
    int n = idx >> 7, c = idx & 127;
    float v = b[c];
    v += x[n * 4 + 0] * w[0 * HID + c];
    v += x[n * 4 + 1] * w[1 * HID + c];
    v += x[n * 4 + 2] * w[2 * HID + c];
    v += x[n * 4 + 3] * w[3 * HID + c];
    g_h[idx] = v;
}

// ---------------- generic GEMM: C[M x 128] = A[M x K] @ B[K x 128] (+bias)(+add) ----------------
#define BM 64
#define BK 32
__global__ __launch_bounds__(256) void gemm128_kernel(
    const float* __restrict__ A, int lda, const float* __restrict__ B,
    const float* __restrict__ bias, const float* __restrict__ add,
    float* __restrict__ C, int M, int K)
{
    __shared__ float As[BM][BK];     // [m][k]
    __shared__ float Bs[BK][HID];    // [k][n]
    int tid = threadIdx.x;
    int tx = tid & 31;    // column group: cols tx*4 .. tx*4+3
    int ty = tid >> 5;    // row group:  rows ty*8 .. ty*8+7
    int m0 = blockIdx.x * BM;

    float acc[8][4];
#pragma unroll
    for (int i = 0; i < 8; ++i)
#pragma unroll
        for (int j = 0; j < 4; ++j) acc[i][j] = 0.f;

    for (int k0 = 0; k0 < K; k0 += BK) {
        // A tile: 64x32 = 512 float4, 2 per thread
#pragma unroll
        for (int it = 0; it < 2; ++it) {
            int idx = tid + it * 256;
            int row = idx >> 3;
            int c4 = idx & 7;
            int gr = m0 + row;
            float4 v = make_float4(0.f, 0.f, 0.f, 0.f);
            if (gr < M) v = *(const float4*)&A[(size_t)gr * lda + k0 + c4 * 4];
            *(float4*)&As[row][c4 * 4] = v;
        }
        // B tile: 32x128 = 1024 float4, 4 per thread
#pragma unroll
        for (int it = 0; it < 4; ++it) {
            int row = (tid >> 5) + it * 8;
            int c4 = tid & 31;
            float4 v = *(const float4*)&B[(size_t)(k0 + row) * HID + c4 * 4];
            *(float4*)&Bs[row][c4 * 4] = v;
        }
        __syncthreads();
#pragma unroll
        for (int kk = 0; kk < BK; ++kk) {
            float4 b4 = *(float4*)&Bs[kk][tx * 4];
#pragma unroll
            for (int i = 0; i < 8; ++i) {
                float a = As[ty * 8 + i][kk];
                acc[i][0] += a * b4.x;
                acc[i][1] += a * b4.y;
                acc[i][2] += a * b4.z;
                acc[i][3] += a * b4.w;
            }
        }
        __syncthreads();
    }

    int c = tx * 4;
    float4 bv = make_float4(0.f, 0.f, 0.f, 0.f);
    if (bias) bv = *(const float4*)&bias[c];
#pragma unroll
    for (int i = 0; i < 8; ++i) {
        int m = m0 + ty * 8 + i;
        if (m < M) {
            float4 r;
            r.x = acc[i][0] + bv.x;
            r.y = acc[i][1] + bv.y;
            r.z = acc[i][2] + bv.z;
            r.w = acc[i][3] + bv.w;
            if (add) {
                float4 av = *(const float4*)&add[(size_t)m * HID + c];
                r.x += av.x; r.y += av.y; r.z += av.z; r.w += av.w;
            }
            *(float4*)&C[(size_t)m * HID + c] = r;
        }
    }
}

// ---------------- q1/q2: per-node attention dot products ----------------
// NOTE: attw = att_w + l*259 is NOT 16B-aligned for l>0 -> scalar loads only.
__global__ void q_kernel(const float* __restrict__ h, const float* __restrict__ attw) {
    int gwarp = (blockIdx.x * blockDim.x + threadIdx.x) >> 5;
    int lane = threadIdx.x & 31;
    if (gwarp >= NN) return;
    const float* hr = h + (size_t)gwarp * HID;
    float4 hv = *(const float4*)&hr[lane * 4];
    int c = lane * 4;
    float a10 = attw[c + 0], a11 = attw[c + 1], a12 = attw[c + 2], a13 = attw[c + 3];
    float a20 = attw[HID + c + 0], a21 = attw[HID + c + 1], a22 = attw[HID + c + 2], a23 = attw[HID + c + 3];
    float s1 = hv.x * a10 + hv.y * a11 + hv.z * a12 + hv.w * a13;
    float s2 = hv.x * a20 + hv.y * a21 + hv.z * a22 + hv.w * a23;
#pragma unroll
    for (int o = 16; o > 0; o >>= 1) {
        s1 += __shfl_xor_sync(0xffffffffu, s1, o);
        s2 += __shfl_xor_sync(0xffffffffu, s2, o);
    }
    if (lane == 0) { g_q1[gwarp] = s1; g_q2[gwarp] = s2; }
}

// ---------------- S[n, k*128+i] = sin(2*pi*(k+1)*h[n,i]) + cos(...) via recurrence ----------------
__global__ void fk_s_kernel(const float* __restrict__ h) {
    int idx = blockIdx.x * blockDim.x + threadIdx.x;
    if (idx >= NN * HID) return;
    int n = idx >> 7, i = idx & 127;
    float theta = TWO_PI_F * h[idx];
    float s1, c1;
    sincosf(theta, &s1, &c1);
    float s = s1, c = c1;
    float* Srow = g_S + (size_t)n * KFK + i;
    Srow[0] = s + c;
#pragma unroll
    for (int k = 1; k < NFREQ; ++k) {
        float s2 = s * c1 + c * s1;
        float c2 = c * c1 - s * s1;
        s = s2; c = c2;
        Srow[k * HID] = s + c;
    }
}

// ---------------- edge conv: gather, attention, message, scatter-add ----------------
__global__ __launch_bounds__(256) void edge_kernel(
    const int* __restrict__ ei, const float* __restrict__ ea,
    const float* __restrict__ linw,   // + l*259*128
    const float* __restrict__ linb,   // + l*128
    const float* __restrict__ attw,   // + l*259
    const float* __restrict__ attb_p, int l)
{
    __shared__ float s_w0[HID], s_w1[HID], s_w2[HID], s_lb[HID];
    __shared__ float s_awe[3];
    __shared__ float s_attb;
    int tid = threadIdx.x;
    if (tid < HID) {
        s_w0[tid] = linw[256 * HID + tid];
        s_w1[tid] = linw[257 * HID + tid];
        s_w2[tid] = linw[258 * HID + tid];
        s_lb[tid] = linb[tid];
    }
    if (tid < 3) s_awe[tid] = attw[256 + tid];
    if (tid == 3) s_attb = attb_p[l];
    __syncthreads();

    int e = blockIdx.x * 8 + (tid >> 5);
    if (e >= NE) return;
    int lane = tid & 31;
    int src = ei[e];
    int dst = ei[NE + e];
    float e0 = ea[e * 3 + 0], e1 = ea[e * 3 + 1], e2 = ea[e * 3 + 2];
    float lg = g_q1[dst] + g_q2[src] + e0 * s_awe[0] + e1 * s_awe[1] + e2 * s_awe[2] + s_attb;
    float alpha = 1.f / (1.f + expf(-lg));
    int c = lane * 4;
    float4 v1 = *(const float4*)&g_p1[(size_t)dst * HID + c];
    float4 v2 = *(const float4*)&g_p2[(size_t)src * HID + c];
    float m0 = alpha * (v1.x + v2.x + e0 * s_w0[c + 0] + e1 * s_w1[c + 0] + e2 * s_w2[c + 0] + s_lb[c + 0]);
    float m1 = alpha * (v1.y + v2.y + e0 * s_w0[c + 1] + e1 * s_w1[c + 1] + e2 * s_w2[c + 1] + s_lb[c + 1]);
    float m2 = alpha * (v1.z + v2.z + e0 * s_w0[c + 2] + e1 * s_w1[c + 2] + e2 * s_w2[c + 2] + s_lb[c + 2]);
    float m3 = alpha * (v1.w + v2.w + e0 * s_w0[c + 3] + e1 * s_w1[c + 3] + e2 * s_w2[c + 3] + s_lb[c + 3]);
    float* outp = &g_hconv[(size_t)dst * HID + c];
    atomicAdd(outp + 0, m0);
    atomicAdd(outp + 1, m1);
    atomicAdd(outp + 2, m2);
    atomicAdd(outp + 3, m3);
}

// ---------------- batchnorm ----------------
__global__ void bn_stat_kernel(const float* __restrict__ h, int rows_per_block) {
    int c = threadIdx.x;  // 128 threads
    int r0 = blockIdx.x * rows_per_block;
    int r1 = min(NN, r0 + rows_per_block);
    float s = 0.f, ss = 0.f;
    for (int r = r0; r < r1; ++r) {
        float v = h[(size_t)r * HID + c];
        s += v; ss += v * v;
    }
    atomicAdd(&g_stats[c], s);
    atomicAdd(&g_stats[HID + c], ss);
}

__global__ void bn_apply_kernel(float* __restrict__ h,
                                const float* __restrict__ g,
                                const float* __restrict__ b) {
    int idx = blockIdx.x * blockDim.x + threadIdx.x;
    if (idx >= NN * HID) return;
    int c = idx & 127;
    const float invN = 1.f / (float)NN;
    float mu = g_stats[c] * invN;
    float var = g_stats[HID + c] * invN - mu * mu;
    float rstd = rsqrtf(var + 1e-5f);
    float v = (h[idx] - mu) * rstd * g[c] + b[c];
    h[idx] = fmaxf(v, 0.f);
}

// ---------------- attention pooling ----------------
__device__ __forceinline__ unsigned float_key(float f) {
    unsigned u = __float_as_uint(f);
    return (u & 0x80000000u) ? ~u : (u | 0x80000000u);
}

__global__ void pool_logit_kernel(const float* __restrict__ h,
                                  const float* __restrict__ pool_w,
                                  const float* __restrict__ pool_b) {
    int gwarp = (blockIdx.x * blockDim.x + threadIdx.x) >> 5;
    int lane = threadIdx.x & 31;
    if (gwarp >= NN) return;
    float4 hv = *(const float4*)&h[(size_t)gwarp * HID + lane * 4];
    float4 wv = *(const float4*)&pool_w[lane * 4];
    float s = hv.x * wv.x + hv.y * wv.y + hv.z * wv.z + hv.w * wv.w;
#pragma unroll
    for (int o = 16; o > 0; o >>= 1) s += __shfl_xor_sync(0xffffffffu, s, o);
    if (lane == 0) {
        s += pool_b[0];
        g_logits[gwarp] = s;
        atomicMax(&g_umax, float_key(s));
    }
}

__global__ void pool_sumexp_kernel() {
    unsigned k = g_umax;
    float maxv = (k & 0x80000000u) ? __uint_as_float(k ^ 0x80000000u)
                                   : __uint_as_float(~k);
    int i = blockIdx.x * blockDim.x + threadIdx.x;
    int stride = gridDim.x * blockDim.x;
    float local = 0.f;
    for (; i < NN; i += stride) local += expf(g_logits[i] - maxv);
#pragma unroll
    for (int o = 16; o > 0; o >>= 1) local += __shfl_xor_sync(0xffffffffu, local, o);
    __shared__ float ws[8];
    int lane = threadIdx.x & 31, wid = threadIdx.x >> 5;
    if (lane == 0) ws[wid] = local;
    __syncthreads();
    if (wid == 0) {
        float v = (lane < (blockDim.x >> 5)) ? ws[lane] : 0.f;
#pragma unroll
        for (int o = 16; o > 0; o >>= 1) v += __shfl_xor_sync(0xffffffffu, v, o);
        if (lane == 0) atomicAdd(&g_sumexp, v);
    }
}

__global__ void pool_scatter_kernel(const float* __restrict__ h,
                                    const int* __restrict__ batch) {
    int gwarp = (blockIdx.x * blockDim.x + threadIdx.x) >> 5;
    int lane = threadIdx.x & 31;
    if (gwarp >= NN) return;
    unsigned k = g_umax;
    float maxv = (k & 0x80000000u) ? __uint_as_float(k ^ 0x80000000u)
                                   : __uint_as_float(~k);
    float w = expf(g_logits[gwarp] - maxv) / g_sumexp;
    int b = batch[gwarp];
    int c = lane * 4;
    float4 hv = *(const float4*)&h[(size_t)gwarp * HID + c];
    float* outp = &g_pooled[b * HID + c];
    atomicAdd(outp + 0, w * hv.x);
    atomicAdd(outp + 1, w * hv.y);
    atomicAdd(outp + 2, w * hv.z);
    atomicAdd(outp + 3, w * hv.w);
}

// ---------------- heads ----------------
__global__ __launch_bounds__(128) void head_kernel(
    const float* __restrict__ sg_table, const int* __restrict__ sgidx,
    const float* __restrict__ hw1, const float* __restrict__ hb1,
    const float* __restrict__ w2e, const float* __restrict__ b2e,
    const float* __restrict__ w2s, const float* __restrict__ b2s,
    const float* __restrict__ w2c, const float* __restrict__ b2c,
    const float* __restrict__ w2m, const float* __restrict__ b2m,
    float* __restrict__ out)
{
    int b = blockIdx.x;
    int t = threadIdx.x;  // 128
    __shared__ float comb[2 * HID];
    __shared__ float z[HID];
    comb[t] = g_pooled[b * HID + t];
    comb[HID + t] = sg_table[sgidx[b] * HID + t];
    __syncthreads();

    const float* w2arr[4] = { w2e, w2s, w2c, w2m };
    const float* b2arr[4] = { b2e, b2s, b2c, b2m };
    const int od[4] = { 1, 3, 7, 3 };
    const int off[4] = { 0, NB * 1, NB * 4, NB * 11 };  // 0, 64, 256, 704

    for (int i = 0; i < 4; ++i) {
        float accz = hb1[i * HID + t];
        const float* W = hw1 + (size_t)i * 2 * HID * HID;
#pragma unroll 8
        for (int j = 0; j < 2 * HID; ++j) accz += comb[j] * W[j * HID + t];
        z[t] = fmaxf(accz, 0.f);
        __syncthreads();
        if (t < od[i]) {
            const float* w2 = w2arr[i];
            float acc = b2arr[i][t];
            for (int j = 0; j < HID; ++j) acc += z[j] * w2[j * od[i] + t];
            out[off[i] + b * od[i] + t] = acc;
        }
        __syncthreads();
    }
}

// ---------------- host ----------------
extern "C" void kernel_launch(void* const* d_in, const int* in_sizes, int n_in,
                              void* d_out, int out_size) {
    const float* x        = (const float*)d_in[0];
    const int*   ei       = (const int*)d_in[1];
    const float* ea       = (const float*)d_in[2];
    const int*   batch    = (const int*)d_in[3];
    const int*   sgidx    = (const int*)d_in[4];
    const float* node_w   = (const float*)d_in[5];
    const float* node_b   = (const float*)d_in[6];
    const float* sg_table = (const float*)d_in[7];
    const float* lin_w    = (const float*)d_in[8];
    const float* lin_b    = (const float*)d_in[9];
    const float* att_w    = (const float*)d_in[10];
    const float* att_b    = (const float*)d_in[11];
    const float* fk_w     = (const float*)d_in[12];
    const float* fk_b     = (const float*)d_in[13];
    const float* bn_g     = (const float*)d_in[14];
    const float* bn_b     = (const float*)d_in[15];
    const float* pool_w   = (const float*)d_in[16];
    const float* pool_b   = (const float*)d_in[17];
    const float* head_w1  = (const float*)d_in[18];
    const float* head_b1  = (const float*)d_in[19];
    const float* w2e = (const float*)d_in[20];
    const float* b2e = (const float*)d_in[21];
    const float* w2s = (const float*)d_in[22];
    const float* b2s = (const float*)d_in[23];
    const float* w2c = (const float*)d_in[24];
    const float* b2c = (const float*)d_in[25];
    const float* w2m = (const float*)d_in[26];
    const float* b2m = (const float*)d_in[27];
    float* out = (float*)d_out;

    float *p_h, *p_p1, *p_p2, *p_hconv, *p_S, *p_stats;
    cudaGetSymbolAddress((void**)&p_h, g_h);
    cudaGetSymbolAddress((void**)&p_p1, g_p1);
    cudaGetSymbolAddress((void**)&p_p2, g_p2);
    cudaGetSymbolAddress((void**)&p_hconv, g_hconv);
    cudaGetSymbolAddress((void**)&p_S, g_S);
    cudaGetSymbolAddress((void**)&p_stats, g_stats);

    const int elem_blocks = (NN * HID + 255) / 256;   // 10000
    const int gemm_blocks = (NN + BM - 1) / BM;       // 313
    const int warp_blocks = (NN + 7) / 8;             // 2500 (8 warps/block)
    const int edge_blocks = (NE + 7) / 8;             // 40000

    // h = x @ node_w + node_b
    node_embed_kernel<<<elem_blocks, 256>>>(x, node_w, node_b);

    for (int l = 0; l < DEPTH; ++l) {
        const float* lw = lin_w + (size_t)l * 259 * HID;
        const float* lb = lin_b + (size_t)l * HID;
        const float* aw = att_w + (size_t)l * 259;

        // per-node projections p1 = h @ W_dst, p2 = h @ W_src
        gemm128_kernel<<<gemm_blocks, 256>>>(p_h, HID, lw, nullptr, nullptr, p_p1, NN, HID);
        gemm128_kernel<<<gemm_blocks, 256>>>(p_h, HID, lw + 128 * HID, nullptr, nullptr, p_p2, NN, HID);
        // attention scalars
        q_kernel<<<warp_blocks, 256>>>(p_h, aw);
        // Fourier features from h (before h is overwritten)
        fk_s_kernel<<<elem_blocks, 256>>>(p_h);
        // edge conv scatter
        zero_kernel<<<2048, 256>>>(p_hconv, NN * HID);
        edge_kernel<<<edge_blocks, 256>>>(ei, ea, lw, lb, aw, att_b, l);
        // h = S @ fk_w[l] + fk_b[l] + h_conv
        gemm128_kernel<<<gemm_blocks, 256>>>(p_S, KFK, fk_w + (size_t)l * KFK * HID,
                                             fk_b + (size_t)l * HID, p_hconv, p_h, NN, KFK);
        // batchnorm (training stats) + relu
        zero_kernel<<<1, 256>>>(p_stats, 2 * HID);
        bn_stat_kernel<<<160, 128>>>(p_h, (NN + 159) / 160);
        bn_apply_kernel<<<elem_blocks, 256>>>(p_h, bn_g + (size_t)l * HID, bn_b + (size_t)l * HID);
    }

    // attention pooling over all nodes
    pool_init_kernel<<<32, 256>>>();
    pool_logit_kernel<<<warp_blocks, 256>>>(p_h, pool_w, pool_b);
    pool_sumexp_kernel<<<80, 256>>>();
    pool_scatter_kernel<<<warp_blocks, 256>>>(p_h, batch);

    // heads -> out layout: energy[64] | stability[64*3] | crystal[64*7] | material[64*3]
    head_kernel<<<NB, 128>>>(sg_table, sgidx, head_w1, head_b1,
                             w2e, b2e, w2s, b2s, w2c, b2c, w2m, b2m, out);
}